// round 10
// baseline (speedup 1.0000x reference)
#include <cuda_runtime.h>

#define FULL 0xFFFFFFFFu
#define NLOG2E (-1.4426950408889634f)

__device__ __forceinline__ unsigned long long pack2(float a, float b) {
    unsigned long long r;
    asm("mov.b64 %0, {%1, %2};" : "=l"(r) : "f"(a), "f"(b));
    return r;
}
__device__ __forceinline__ void unpack2(unsigned long long p, float& a, float& b) {
    asm("mov.b64 {%0, %1}, %2;" : "=f"(a), "=f"(b) : "l"(p));
}
__device__ __forceinline__ unsigned long long fma2(unsigned long long a,
                                                   unsigned long long b,
                                                   unsigned long long c) {
    unsigned long long d;
    asm("fma.rn.f32x2 %0, %1, %2, %3;" : "=l"(d) : "l"(a), "l"(b), "l"(c));
    return d;
}
__device__ __forceinline__ unsigned long long add2(unsigned long long a,
                                                   unsigned long long b) {
    unsigned long long d;
    asm("add.rn.f32x2 %0, %1, %2;" : "=l"(d) : "l"(a), "l"(b));
    return d;
}
__device__ __forceinline__ float ex2(float x) {
    float r; asm("ex2.approx.f32 %0, %1;" : "=f"(r) : "f"(x)); return r;
}
__device__ __forceinline__ float rcp(float x) {
    float r; asm("rcp.approx.f32 %0, %1;" : "=f"(r) : "f"(x)); return r;
}
// sigma from pre-scaled argument zs = -z*log2e :  1/(1+2^zs)
__device__ __forceinline__ float sigmoid_scaled(float zs) {
    return rcp(1.0f + ex2(zs));
}
__device__ __forceinline__ float fast_sigmoid(float x) {
    return rcp(1.0f + ex2(x * NLOG2E));
}

// One CTA per TWO batches, 160 threads, grid 128 (one CTA/SM, single wave).
// Round 10: UNIT-PER-THREAD layer-0. Thread t<128 owns ALL FOUR gate columns
// of unit u = t&63 for batch bsel = t>>6 (warps 0-1: batch0, 2-3: batch1).
//   - one h broadcast (16 LDS.128) feeds 4 gate dots -> LDS halved vs R4
//   - gates i,j,f,o are thread-local -> NO shfl in the tail
//   - weights pre-scaled by -log2e (j by -2log2e; forget bias folded) so each
//     sigmoid is EX2 -> FADD -> RCP with no leading FMUL
// Threads 128..159 (warp 4): layer-1 (units=1) + dense for both batches
// (lane halves), one step lagged, accumulation split into 2 chains.
// One __syncthreads per step.
__global__ __launch_bounds__(160, 1)
void lstm_stack_kernel(const float* __restrict__ x,
                       const float* __restrict__ W0,
                       const float* __restrict__ b0,
                       const float* __restrict__ W1,
                       const float* __restrict__ b1,
                       const float* __restrict__ Wd,
                       const float* __restrict__ bd,
                       float* __restrict__ out)
{
    constexpr int T = 2048;

    const int bb   = blockIdx.x;      // batch pair
    const int tid  = threadIdx.x;
    const int lane = tid & 31;
    const int wid  = tid >> 5;

    __shared__ __align__(16) float x_sh[2][T];
    __shared__ __align__(16) float h_sh[2][2][64];   // [buffer][batch][unit]
    __shared__ float red[5];
    __shared__ float inv_sh[2];

    // ---- Phase 0: load both x tiles, l2-normalize over time ----
    for (int bi = 0; bi < 2; ++bi) {
        const float* xb = x + (2 * bb + bi) * T;
        float ps = 0.f;
        for (int i = tid; i < T; i += 160) {
            float v = xb[i];
            x_sh[bi][i] = v;
            ps = fmaf(v, v, ps);
        }
        #pragma unroll
        for (int o = 16; o > 0; o >>= 1) ps += __shfl_xor_sync(FULL, ps, o);
        if (lane == 0) red[wid] = ps;
        __syncthreads();
        if (tid == 0) {
            float s = 0.f;
            #pragma unroll
            for (int i = 0; i < 5; ++i) s += red[i];
            inv_sh[bi] = rsqrtf(fmaxf(s, 1e-12f));
        }
        __syncthreads();               // also protects red[] reuse
    }
    {
        float i0 = inv_sh[0], i1 = inv_sh[1];
        for (int i = tid; i < T; i += 160) {
            x_sh[0][i] *= i0;
            x_sh[1][i] *= i1;
        }
    }
    if (tid < 128) ((float*)h_sh[0])[tid] = 0.f;   // h_{-1} = 0, both batches
    // (ordered by the sync at the top of the main loop)

    // ---- Per-thread persistent state / weights ----
    const int u    = tid & 63;
    const int bsel = (tid >> 6) & 1;
    // gate scale factors: i,f,o -> -log2e ; j -> -2log2e (tanh via sigma(2j))
    unsigned long long wg[4][16];   // [gate][k-pair-quad]  f32x2 packed
    float wx[4], bz[4];
    float c0 = 0.f;

    // layer-1 (warp 4) state: lanes 0-15 -> batch0, 16-31 -> batch1
    const int l1b  = lane >> 4;
    const int l1g  = lane & 3;
    const int l1bk = (lane >> 2) & 3;
    float w1r[16];
    float w1h = 0.f, b1v = 0.f, wdv = 0.f, bdv = 0.f;
    float c1 = 0.f, h1 = 0.f;

    if (tid < 128) {
        #pragma unroll
        for (int g = 0; g < 4; ++g) {
            const float sc = (g == 1) ? (2.0f * NLOG2E) : NLOG2E;
            const int col = g * 64 + u;
            wx[g] = W0[col] * sc;
            bz[g] = (b0[col] + (g == 2 ? 1.0f : 0.0f)) * sc;  // fold FORGET_BIAS
            #pragma unroll
            for (int p = 0; p < 16; ++p) {
                float w0v = W0[(1 + 4 * p) * 256 + col] * sc;
                float w1v = W0[(2 + 4 * p) * 256 + col] * sc;
                float w2v = W0[(3 + 4 * p) * 256 + col] * sc;
                float w3v = W0[(4 + 4 * p) * 256 + col] * sc;
                // two f32x2 per 4-wide h chunk: stored interleaved per chain
                wg[g][p] = pack2(w0v, w1v);
                // second pair goes in the alternate chain slot
                // (store in upper half of the table: index p+? keep simple:)
                // we pack pairs (w0,w1) and (w2,w3) in adjacent entries
                // -> use a flat [32] layout per gate instead:
                ((unsigned long long*)wg[g])[p] = pack2(w0v, w1v);
                // placeholder; real layout set below
                (void)w2v; (void)w3v;
            }
        }
        // Re-load with flat layout: wgf[g][2p] = (w_{2p*2}, w_{2p*2+1})
        // Simpler: directly fill 32 pairs per gate in a second pass.
    } else {
        #pragma unroll
        for (int j = 0; j < 16; ++j)
            w1r[j] = W1[(l1bk + 4 * j) * 4 + l1g];
        w1h = W1[64 * 4 + l1g];
        b1v = b1[l1g];
        wdv = Wd[0];
        bdv = bd[0];
    }

    // Full flat weight tables (overwrites the placeholder fill above).
    unsigned long long wflat[4][32];
    if (tid < 128) {
        #pragma unroll
        for (int g = 0; g < 4; ++g) {
            const float sc = (g == 1) ? (2.0f * NLOG2E) : NLOG2E;
            const int col = g * 64 + u;
            #pragma unroll
            for (int p = 0; p < 32; ++p) {
                float a  = W0[(1 + 2 * p) * 256 + col] * sc;
                float bv = W0[(2 + 2 * p) * 256 + col] * sc;
                wflat[g][p] = pack2(a, bv);
            }
        }
    } else {
        #pragma unroll
        for (int g = 0; g < 4; ++g)
            #pragma unroll
            for (int p = 0; p < 32; ++p)
                wflat[g][p] = 0ull;
    }

    // ---- Main recurrence ----
    #pragma unroll 1
    for (int t = 0; t <= T; ++t) {
        const int tt = (t < T) ? t : 0;
        const float xt = x_sh[bsel][tt];
        __syncthreads();                 // h_sh[t&1] = h_{t-1} now valid
        const int cur = t & 1;
        if (tid < 128) {
            if (t < T) {
                const ulonglong2* hp = (const ulonglong2*)h_sh[cur][bsel];
                // 8 accumulator chains: 2 per gate
                unsigned long long acc0[4], acc1[4];
                #pragma unroll
                for (int g = 0; g < 4; ++g) {
                    acc0[g] = pack2(fmaf(xt, wx[g], bz[g]), 0.f);
                    acc1[g] = pack2(0.f, 0.f);
                }
                #pragma unroll
                for (int i = 0; i < 16; ++i) {
                    ulonglong2 hv = hp[i];   // h[4i..4i+3] as two f32x2
                    #pragma unroll
                    for (int g = 0; g < 4; ++g) {
                        acc0[g] = fma2(hv.x, wflat[g][2 * i],     acc0[g]);
                        acc1[g] = fma2(hv.y, wflat[g][2 * i + 1], acc1[g]);
                    }
                }
                float z[4];
                #pragma unroll
                for (int g = 0; g < 4; ++g) {
                    float lo, hi;
                    unpack2(add2(acc0[g], acc1[g]), lo, hi);
                    z[g] = lo + hi;      // already scaled by -log2e (x2 for j)
                }
                // gates (no shfl): i=z0, j=z1, f=z2 (bias folded), o=z3
                float si = sigmoid_scaled(z[0]);
                float tj = 2.f * sigmoid_scaled(z[1]) - 1.f;   // tanh(j)
                float sf = sigmoid_scaled(z[2]);
                float so = sigmoid_scaled(z[3]);
                c0 = fmaf(sf, c0, si * tj);
                float tc = 2.f * fast_sigmoid(c0 + c0) - 1.f;  // tanh(c)
                h_sh[cur ^ 1][bsel][u] = so * tc;
            }
        } else {
            if (t >= 1) {
                // layer-1 for step s = t-1, input h_sh[cur][l1b]
                const float* hv = h_sh[cur][l1b];
                float p0 = 0.f, p1 = 0.f;        // split accumulation chains
                #pragma unroll
                for (int j = 0; j < 8; ++j) {
                    p0 = fmaf(hv[l1bk + 4 * (2 * j)],     w1r[2 * j],     p0);
                    p1 = fmaf(hv[l1bk + 4 * (2 * j + 1)], w1r[2 * j + 1], p1);
                }
                float p = p0 + p1;
                p += __shfl_xor_sync(FULL, p, 4);    // stays within 16-lane half
                p += __shfl_xor_sync(FULL, p, 8);
                float z1 = fmaf(h1, w1h, p + b1v);

                float zz = (l1g == 2) ? (z1 + 1.0f) : z1;
                float sv = (l1g == 1) ? (zz + zz) : zz;
                float sg = fast_sigmoid(sv);
                float r  = (l1g == 1) ? (2.f * sg - 1.f) : sg;

                float ri = __shfl_sync(FULL, r, 0, 4);
                float rj = __shfl_sync(FULL, r, 1, 4);
                float rf = __shfl_sync(FULL, r, 2, 4);
                float ro = __shfl_sync(FULL, r, 3, 4);
                c1 = fmaf(rf, c1, ri * rj);
                float th = 2.f * fast_sigmoid(c1 + c1) - 1.f;
                h1 = ro * th;
                if ((lane & 15) == 0)
                    out[(2 * bb + l1b) * T + (t - 1)] = fmaf(h1, wdv, bdv);
            }
        }
    }
}

extern "C" void kernel_launch(void* const* d_in, const int* in_sizes, int n_in,
                              void* d_out, int out_size) {
    const float* x  = (const float*)d_in[0];
    const float* W0 = (const float*)d_in[1];
    const float* b0 = (const float*)d_in[2];
    const float* W1 = (const float*)d_in[3];
    const float* b1 = (const float*)d_in[4];
    const float* Wd = (const float*)d_in[5];
    const float* bd = (const float*)d_in[6];
    float* out = (float*)d_out;
    lstm_stack_kernel<<<128, 160>>>(x, W0, b0, W1, b1, Wd, bd, out);
}

// round 11
// speedup vs baseline: 1.5299x; 1.5299x over previous
#include <cuda_runtime.h>

#define FULL 0xFFFFFFFFu

__device__ __forceinline__ unsigned long long pack2(float a, float b) {
    unsigned long long r;
    asm("mov.b64 %0, {%1, %2};" : "=l"(r) : "f"(a), "f"(b));
    return r;
}
__device__ __forceinline__ void unpack2(unsigned long long p, float& a, float& b) {
    asm("mov.b64 {%0, %1}, %2;" : "=f"(a), "=f"(b) : "l"(p));
}
__device__ __forceinline__ unsigned long long fma2(unsigned long long a,
                                                   unsigned long long b,
                                                   unsigned long long c) {
    unsigned long long d;
    asm("fma.rn.f32x2 %0, %1, %2, %3;" : "=l"(d) : "l"(a), "l"(b), "l"(c));
    return d;
}
__device__ __forceinline__ unsigned long long add2(unsigned long long a,
                                                   unsigned long long b) {
    unsigned long long d;
    asm("add.rn.f32x2 %0, %1, %2;" : "=l"(d) : "l"(a), "l"(b));
    return d;
}

__device__ __forceinline__ float fast_sigmoid(float x) {
    return __fdividef(1.0f, 1.0f + __expf(-x));
}

// ONE batch per CTA, 160 threads, grid 256, TWO CTAs per SM.
// The two co-resident CTAs have independent __syncthreads barriers, so their
// phases drift: one CTA's exposed nonlinear tail + barrier hides under the
// other CTA's 128-cycle fma burst — the overlap that phase-locked warps
// (R6) and intra-thread reordering (R7/R9) could not deliver.
// Threads 0..127: layer-0; thread = (unit u = t>>1, type = t&1); type0 owns
// gate columns (i,j), type1 owns (f,o); weights register-resident f32x2.
// One LDS.128 per h-quad feeds both gates; one shfl_xor(1) exchanges
// sigma(f) <-> sigma(i)*tanh(j). Threads 128..159 (warp 4): layer-1
// (units=1) + dense, one step lagged. One __syncthreads per step.
__global__ __launch_bounds__(160, 2)
void lstm_stack_kernel(const float* __restrict__ x,
                       const float* __restrict__ W0,
                       const float* __restrict__ b0,
                       const float* __restrict__ W1,
                       const float* __restrict__ b1,
                       const float* __restrict__ Wd,
                       const float* __restrict__ bd,
                       float* __restrict__ out)
{
    constexpr int T = 2048;

    const int bb   = blockIdx.x;      // batch
    const int tid  = threadIdx.x;
    const int lane = tid & 31;
    const int wid  = tid >> 5;

    __shared__ __align__(16) float x_sh[T];
    __shared__ __align__(16) float h_sh[2][64];
    __shared__ float red[5];
    __shared__ float inv_sh;

    // ---- Phase 0: load x tile, l2-normalize over time ----
    const float* xb = x + bb * T;
    float ps = 0.f;
    for (int i = tid; i < T; i += 160) {
        float v = xb[i];
        x_sh[i] = v;
        ps = fmaf(v, v, ps);
    }
    #pragma unroll
    for (int o = 16; o > 0; o >>= 1) ps += __shfl_xor_sync(FULL, ps, o);
    if (lane == 0) red[wid] = ps;
    if (tid < 64) h_sh[0][tid] = 0.f;   // h_{-1} = 0
    __syncthreads();
    if (tid == 0) {
        float s = 0.f;
        #pragma unroll
        for (int i = 0; i < 5; ++i) s += red[i];
        inv_sh = rsqrtf(fmaxf(s, 1e-12f));
    }
    __syncthreads();
    {
        float inv = inv_sh;
        for (int i = tid; i < T; i += 160) x_sh[i] *= inv;
    }
    // (ordered by the sync at the top of the main loop)

    // ---- Per-thread persistent state / weights ----
    const int u    = tid >> 1;
    const int type = tid & 1;           // 0: (i,j)   1: (f,o)
    unsigned long long wpa[32], wpb[32];
    float wxa = 0.f, wxb = 0.f, ba = 0.f, bb2 = 0.f;
    float c0 = 0.f;

    // layer-1 (warp 4) state
    const int l1g  = lane & 3;
    const int l1bk = lane >> 2;         // 8 banks
    float w1r[8];
    float w1h = 0.f, b1v = 0.f, wdv = 0.f, bdv = 0.f;
    float c1 = 0.f, h1 = 0.f;

    if (tid < 128) {
        const int ca = u + (type ? 128 : 0);   // i or f column
        const int cb = ca + 64;                // j or o column
        wxa = W0[ca];
        wxb = W0[cb];
        ba  = b0[ca] + (type ? 1.0f : 0.0f);   // fold FORGET_BIAS
        bb2 = b0[cb];
        #pragma unroll
        for (int p = 0; p < 32; ++p) {
            wpa[p] = pack2(W0[(1 + 2 * p) * 256 + ca], W0[(2 + 2 * p) * 256 + ca]);
            wpb[p] = pack2(W0[(1 + 2 * p) * 256 + cb], W0[(2 + 2 * p) * 256 + cb]);
        }
    } else {
        #pragma unroll
        for (int j = 0; j < 8; ++j)
            w1r[j] = W1[(l1bk + 8 * j) * 4 + l1g];
        w1h = W1[64 * 4 + l1g];
        b1v = b1[l1g];
        wdv = Wd[0];
        bdv = bd[0];
    }

    float* outb = out + bb * T;

    // ---- Main recurrence: t = 0..T. Layer-0 active for t<T, layer-1
    // processes step t-1 (final iteration drains layer-1). ----
    #pragma unroll 1
    for (int t = 0; t <= T; ++t) {
        const int tt = (t < T) ? t : 0;
        const float xt = x_sh[tt];       // read-only prefetch, no barrier dep
        __syncthreads();                 // h_sh[t&1] = h_{t-1} now valid
        const int cur = t & 1;
        if (tid < 128) {
            if (t < T) {
                const ulonglong2* hp = (const ulonglong2*)h_sh[cur];
                unsigned long long a0 = pack2(fmaf(xt, wxa, ba), 0.f);
                unsigned long long a1 = pack2(0.f, 0.f);
                unsigned long long e0 = pack2(fmaf(xt, wxb, bb2), 0.f);
                unsigned long long e1 = pack2(0.f, 0.f);
                #pragma unroll
                for (int i = 0; i < 16; ++i) {
                    ulonglong2 hv = hp[i];   // one LDS.128 feeds both gates
                    a0 = fma2(hv.x, wpa[2 * i],     a0);
                    a1 = fma2(hv.y, wpa[2 * i + 1], a1);
                    e0 = fma2(hv.x, wpb[2 * i],     e0);
                    e1 = fma2(hv.y, wpb[2 * i + 1], e1);
                }
                float za, zb;
                {
                    float lo, hi;
                    unpack2(add2(a0, a1), lo, hi); za = lo + hi;
                    unpack2(add2(e0, e1), lo, hi); zb = lo + hi;
                }

                // type0: sa = sigma(i), rb = tanh(j); sends sa*rb.
                // type1: sa = sigma(f+1) (bias folded), rb = sigma(o); sends sa.
                float sa = fast_sigmoid(za);
                float sb = fast_sigmoid(type ? zb : (zb + zb));
                float rb = type ? sb : (2.f * sb - 1.f);
                float send = type ? sa : (sa * rb);
                float recv = __shfl_xor_sync(FULL, send, 1);
                float fg  = type ? sa : recv;
                float inc = type ? recv : send;
                c0 = fmaf(fg, c0, inc);
                float th = 2.f * fast_sigmoid(c0 + c0) - 1.f;
                float h  = rb * th;       // valid on type1 (rb = sigma(o))
                if (type) h_sh[cur ^ 1][u] = h;
            }
        } else {
            if (t >= 1) {
                // layer-1 for step s = t-1, input h_sh[cur] = h^{(0)}_{t-1}
                const float* hv = h_sh[cur];
                float p0 = 0.f, p1 = 0.f;
                #pragma unroll
                for (int j = 0; j < 4; ++j) {
                    p0 = fmaf(hv[l1bk + 8 * (2 * j)],     w1r[2 * j],     p0);
                    p1 = fmaf(hv[l1bk + 8 * (2 * j + 1)], w1r[2 * j + 1], p1);
                }
                float p = p0 + p1;
                p += __shfl_xor_sync(FULL, p, 4);
                p += __shfl_xor_sync(FULL, p, 8);
                p += __shfl_xor_sync(FULL, p, 16);
                float z1 = fmaf(h1, w1h, p + b1v);

                float zz = (l1g == 2) ? (z1 + 1.0f) : z1;
                float sv = (l1g == 1) ? (zz + zz) : zz;
                float sg = fast_sigmoid(sv);
                float r  = (l1g == 1) ? (2.f * sg - 1.f) : sg;

                float ri = __shfl_sync(FULL, r, 0, 4);
                float rj = __shfl_sync(FULL, r, 1, 4);
                float rf = __shfl_sync(FULL, r, 2, 4);
                float ro = __shfl_sync(FULL, r, 3, 4);
                c1 = fmaf(rf, c1, ri * rj);
                float th = 2.f * fast_sigmoid(c1 + c1) - 1.f;
                h1 = ro * th;
                if (lane == 0) outb[t - 1] = fmaf(h1, wdv, bdv);
            }
        }
    }
}

extern "C" void kernel_launch(void* const* d_in, const int* in_sizes, int n_in,
                              void* d_out, int out_size) {
    const float* x  = (const float*)d_in[0];
    const float* W0 = (const float*)d_in[1];
    const float* b0 = (const float*)d_in[2];
    const float* W1 = (const float*)d_in[3];
    const float* b1 = (const float*)d_in[4];
    const float* Wd = (const float*)d_in[5];
    const float* bd = (const float*)d_in[6];
    float* out = (float*)d_out;
    lstm_stack_kernel<<<256, 160>>>(x, W0, b0, W1, b1, Wd, bd, out);
}